// round 8
// baseline (speedup 1.0000x reference)
#include <cuda_runtime.h>
#include <cuda_fp16.h>
#include <cstdint>

// Conv2D 4096x4096, 15x15, pad=1 -> 4084x4084, + bias.
// R8: mma.sync m16n8k16 (fp16 in, fp32 acc), warp tile widened to 32y x 64x:
// A-window fragments shared across 8-col n-blocks -> 17% fewer ldmatrix
// wavefronts per output. CTA = 128y x 128x, dynamic smem 58.5 KB.

#define KS      15
#define IN_N    4096
#define OUT_N   4084
#define CTA_Y   128            // 4 warps in y
#define CTA_X   128            // 2 warps in x, 64 cols each
#define AROWS   142            // 128 + 14 halo
#define ACOLS   142            // 128 + 14 halo
#define ASTRIDE 152            // elems; 304B: 16B-aligned rows, %32==16 -> conflict-free
#define NDY     KS
#define NFRAG   4              // B fragments per dy (relative shifts -8,0,+8,+16)
#define NWIN    5              // A k-windows per (dy, mh) for 64 cols
#define NBLK    8              // 8-col n-blocks per warp
#define SBF_BYTES (NDY * NFRAG * 32 * 8)               // 15360
#define SA_BYTES  (AROWS * ASTRIDE * 2)                // 43168
#define SMEM_TOTAL (SBF_BYTES + SA_BYTES)

__device__ uint2 gBf[NDY * NFRAG * 32];   // B fragments, exact mma lane layout

__global__ void prep_Bfrag(const float* __restrict__ w)
{
    int idx = blockIdx.x * blockDim.x + threadIdx.x;
    if (idx >= NDY * NFRAG * 32) return;
    const int lane = idx & 31;
    const int d    = (idx >> 5) & 3;
    const int dy   = idx >> 7;
    const int tg   = lane & 3;
    const int gp   = lane >> 2;
    const int base = 8 * (d - 1) - gp;
    float v[4];
    #pragma unroll
    for (int q = 0; q < 4; ++q) {
        const int kl = 2 * tg + (q & 1) + 8 * (q >> 1);
        const int t  = base + kl;
        v[q] = (t >= 0 && t < KS) ? w[dy * KS + t] : 0.0f;
    }
    __half2 lo = __floats2half2_rn(v[0], v[1]);
    __half2 hi = __floats2half2_rn(v[2], v[3]);
    uint2 r;
    r.x = *reinterpret_cast<uint32_t*>(&lo);
    r.y = *reinterpret_cast<uint32_t*>(&hi);
    gBf[idx] = r;
}

__device__ __forceinline__ uint32_t smem_u32(const void* p)
{
    uint32_t a;
    asm("{ .reg .u64 t; cvta.to.shared.u64 t, %1; cvt.u32.u64 %0, t; }"
        : "=r"(a) : "l"(p));
    return a;
}
__device__ __forceinline__ void ldmA(uint32_t a[4], uint32_t addr)
{
    asm volatile("ldmatrix.sync.aligned.m8n8.x4.shared.b16 {%0,%1,%2,%3}, [%4];"
                 : "=r"(a[0]), "=r"(a[1]), "=r"(a[2]), "=r"(a[3]) : "r"(addr));
}
__device__ __forceinline__ void mma16816(float c[4], const uint32_t a[4],
                                         uint32_t b0, uint32_t b1)
{
    asm volatile(
        "mma.sync.aligned.m16n8k16.row.col.f32.f16.f16.f32 "
        "{%0,%1,%2,%3}, {%4,%5,%6,%7}, {%8,%9}, {%0,%1,%2,%3};"
        : "+f"(c[0]), "+f"(c[1]), "+f"(c[2]), "+f"(c[3])
        : "r"(a[0]), "r"(a[1]), "r"(a[2]), "r"(a[3]), "r"(b0), "r"(b1));
}

__global__ __launch_bounds__(256, 2)
void conv2d_mma64_kernel(const float* __restrict__ x,
                         const float* __restrict__ bias,
                         float* __restrict__ out)
{
    extern __shared__ __align__(128) char smem[];
    uint2*  sBf = reinterpret_cast<uint2*>(smem);                // 15360 B
    __half* sA  = reinterpret_cast<__half*>(smem + SBF_BYTES);   // 43168 B

    const int tid  = threadIdx.x;
    const int lane = tid & 31;
    const int wid  = tid >> 5;
    const int wy   = wid >> 1;          // 0..3
    const int wx   = wid & 1;           // 0..1
    const int X0   = blockIdx.x * CTA_X;
    const int Y0   = blockIdx.y * CTA_Y;

    // ---- stage B fragments ----
    for (int i = tid; i < NDY * NFRAG * 32; i += 256)
        sBf[i] = gBf[i];

    // ---- stage A: 142 x 142 fp32 -> fp16, stride 152 (pad cols zeroed) ----
    for (int idx = tid; idx < AROWS * (ASTRIDE / 2); idx += 256) {
        const int r  = idx / (ASTRIDE / 2);
        const int p  = idx - r * (ASTRIDE / 2);
        const int c  = 2 * p;
        const int gy = Y0 - 1 + r;
        const int gx = X0 - 1 + c;
        float v0 = 0.0f, v1 = 0.0f;
        if (c < ACOLS && (unsigned)gy < IN_N) {
            const float* rp = x + (size_t)gy * IN_N;
            if ((unsigned)gx       < IN_N) v0 = rp[gx];
            if ((unsigned)(gx + 1) < IN_N && c + 1 < ACOLS) v1 = rp[gx + 1];
        }
        *reinterpret_cast<__half2*>(&sA[r * ASTRIDE + c]) = __floats2half2_rn(v0, v1);
    }
    __syncthreads();

    // ---- accumulators seeded with bias ----
    const float bval = bias[0];
    float acc[2][NBLK][4];
    #pragma unroll
    for (int m = 0; m < 2; ++m)
        #pragma unroll
        for (int j = 0; j < NBLK; ++j)
            #pragma unroll
            for (int e = 0; e < 4; ++e)
                acc[m][j][e] = bval;

    const uint32_t sA_b = smem_u32(sA);
    // per-lane ldmatrix address: row (lane&15), k-half (lane>>4)*16B, warp x base
    const uint32_t lanepart = sA_b + (uint32_t)((lane & 15) * (ASTRIDE * 2))
                            + (uint32_t)(128 * wx) + (uint32_t)((lane >> 4) << 4);
    const uint32_t sBf_b = smem_u32(sBf);
    const int rowbase = 32 * wy;

    #pragma unroll 1
    for (int dy = 0; dy < NDY; ++dy) {
        uint32_t b[NFRAG][2];
        #pragma unroll
        for (int d = 0; d < NFRAG; ++d) {
            uint32_t addr = sBf_b + (uint32_t)(((dy * NFRAG + d) * 32 + lane) * 8);
            asm volatile("ld.shared.v2.u32 {%0,%1}, [%2];"
                         : "=r"(b[d][0]), "=r"(b[d][1]) : "r"(addr));
        }
        #pragma unroll
        for (int mh = 0; mh < 2; ++mh) {
            const uint32_t rbase = lanepart
                + (uint32_t)((rowbase + 16 * mh + dy) * (ASTRIDE * 2));
            uint32_t a[NWIN][4];
            #pragma unroll
            for (int wnd = 0; wnd < NWIN; ++wnd)
                ldmA(a[wnd], rbase + 32 * wnd);
            #pragma unroll
            for (int nb = 0; nb < NBLK; ++nb) {
                float* c = acc[mh][nb];
                if ((nb & 1) == 0) {
                    mma16816(c, a[nb / 2],     b[1][0], b[1][1]);   // shift  0
                    mma16816(c, a[nb / 2 + 1], b[3][0], b[3][1]);   // shift +16
                } else {
                    mma16816(c, a[(nb - 1) / 2], b[0][0], b[0][1]); // shift -8
                    mma16816(c, a[(nb + 1) / 2], b[2][0], b[2][1]); // shift +8
                }
            }
        }
    }

    // ---- epilogue: D fragments -> gmem (float2 stores) ----
    const int tg = lane & 3;
    const int gp = lane >> 2;
    #pragma unroll
    for (int mh = 0; mh < 2; ++mh)
        #pragma unroll
        for (int nb = 0; nb < NBLK; ++nb) {
            const int col = X0 + 64 * wx + 8 * nb + 2 * tg;
            const int r0  = Y0 + 32 * wy + 16 * mh + gp;
            if (col < OUT_N) {
                if (r0 < OUT_N) {
                    float2 v = make_float2(acc[mh][nb][0], acc[mh][nb][1]);
                    *reinterpret_cast<float2*>(&out[(size_t)r0 * OUT_N + col]) = v;
                }
                if (r0 + 8 < OUT_N) {
                    float2 v = make_float2(acc[mh][nb][2], acc[mh][nb][3]);
                    *reinterpret_cast<float2*>(&out[(size_t)(r0 + 8) * OUT_N + col]) = v;
                }
            }
        }
}

extern "C" void kernel_launch(void* const* d_in, const int* in_sizes, int n_in,
                              void* d_out, int out_size)
{
    const float* x    = (const float*)d_in[0];   // 4096*4096
    const float* w    = (const float*)d_in[1];   // 15*15
    const float* bias = (const float*)d_in[2];   // 1
    float* out        = (float*)d_out;           // 4084*4084

    prep_Bfrag<<<(NDY * NFRAG * 32 + 255) / 256, 256>>>(w);

    cudaFuncSetAttribute(conv2d_mma64_kernel,
                         cudaFuncAttributeMaxDynamicSharedMemorySize, SMEM_TOTAL);

    dim3 grid((OUT_N + CTA_X - 1) / CTA_X,       // 32
              (OUT_N + CTA_Y - 1) / CTA_Y);      // 32
    conv2d_mma64_kernel<<<grid, 256, SMEM_TOTAL>>>(x, bias, out);
}

// round 9
// speedup vs baseline: 1.2610x; 1.2610x over previous
#include <cuda_runtime.h>
#include <cuda_fp16.h>
#include <cstdint>

// Conv2D 4096x4096, 15x15, pad=1 -> 4084x4084, + bias.
// R9: R7 tiling (warp 32y x 32x, CTA 128y x 64x) with intra-iteration load
// batching: per dy, all 4 B LDS.64 + 6 ldmatrix.x4 (both m-halves) issue as
// independent ops before the 16 MMAs -> MLP 3 -> 10, launch_bounds(256,3).

#define KS      15
#define IN_N    4096
#define OUT_N   4084
#define CTA_Y   128            // 4 warps in y
#define CTA_X   64             // 2 warps in x
#define AROWS   142            // 128 + 14 halo
#define ACOLS   80             // 64 + 14 halo + 2 zero pad
#define ASTRIDE 88             // fp16/row; 176B: 16B-aligned, conflict-free ldmatrix
#define NDY     KS
#define NFRAG   4              // B fragments per dy (shifts -8, 0, +8, +16)

__device__ uint2 gBf[NDY * NFRAG * 32];   // B fragments in exact mma lane layout

__global__ void prep_Bfrag(const float* __restrict__ w)
{
    int idx = blockIdx.x * blockDim.x + threadIdx.x;
    if (idx >= NDY * NFRAG * 32) return;
    const int lane = idx & 31;
    const int d    = (idx >> 5) & 3;
    const int dy   = idx >> 7;
    const int tg   = lane & 3;
    const int gp   = lane >> 2;
    const int base = 8 * (d - 1) - gp;
    float v[4];
    #pragma unroll
    for (int q = 0; q < 4; ++q) {
        const int kl = 2 * tg + (q & 1) + 8 * (q >> 1);
        const int t  = base + kl;
        v[q] = (t >= 0 && t < KS) ? w[dy * KS + t] : 0.0f;
    }
    __half2 lo = __floats2half2_rn(v[0], v[1]);
    __half2 hi = __floats2half2_rn(v[2], v[3]);
    uint2 r;
    r.x = *reinterpret_cast<uint32_t*>(&lo);
    r.y = *reinterpret_cast<uint32_t*>(&hi);
    gBf[idx] = r;
}

__device__ __forceinline__ uint32_t smem_u32(const void* p)
{
    uint32_t a;
    asm("{ .reg .u64 t; cvta.to.shared.u64 t, %1; cvt.u32.u64 %0, t; }"
        : "=r"(a) : "l"(p));
    return a;
}
__device__ __forceinline__ void ldmA(uint32_t a[4], uint32_t addr)
{
    asm volatile("ldmatrix.sync.aligned.m8n8.x4.shared.b16 {%0,%1,%2,%3}, [%4];"
                 : "=r"(a[0]), "=r"(a[1]), "=r"(a[2]), "=r"(a[3]) : "r"(addr));
}
__device__ __forceinline__ void mma16816(float c[4], const uint32_t a[4],
                                         uint32_t b0, uint32_t b1)
{
    asm volatile(
        "mma.sync.aligned.m16n8k16.row.col.f32.f16.f16.f32 "
        "{%0,%1,%2,%3}, {%4,%5,%6,%7}, {%8,%9}, {%0,%1,%2,%3};"
        : "+f"(c[0]), "+f"(c[1]), "+f"(c[2]), "+f"(c[3])
        : "r"(a[0]), "r"(a[1]), "r"(a[2]), "r"(a[3]), "r"(b0), "r"(b1));
}

__global__ __launch_bounds__(256, 3)
void conv2d_mma_kernel(const float* __restrict__ x,
                       const float* __restrict__ bias,
                       float* __restrict__ out)
{
    __shared__ __align__(32) __half sA[AROWS * ASTRIDE];   // 24992 B
    __shared__ uint2 sBf[NDY * NFRAG * 32];                // 15360 B

    const int tid  = threadIdx.x;
    const int lane = tid & 31;
    const int wid  = tid >> 5;
    const int wy   = wid >> 1;          // 0..3
    const int wx   = wid & 1;           // 0..1
    const int X0   = blockIdx.x * CTA_X;
    const int Y0   = blockIdx.y * CTA_Y;

    // ---- stage B fragments ----
    for (int i = tid; i < NDY * NFRAG * 32; i += 256)
        sBf[i] = gBf[i];

    // ---- stage A: 142 x 80 fp32 -> fp16 (smem col j <-> input col X0-1+j) ----
    for (int idx = tid; idx < AROWS * (ACOLS / 2); idx += 256) {
        const int r  = idx / (ACOLS / 2);
        const int p  = idx - r * (ACOLS / 2);
        const int gy = Y0 - 1 + r;
        const int gx = X0 - 1 + 2 * p;
        float v0 = 0.0f, v1 = 0.0f;
        if ((unsigned)gy < IN_N) {
            const float* rp = x + (size_t)gy * IN_N;
            if ((unsigned)gx       < IN_N) v0 = rp[gx];
            if ((unsigned)(gx + 1) < IN_N) v1 = rp[gx + 1];
        }
        *reinterpret_cast<__half2*>(&sA[r * ASTRIDE + 2 * p]) = __floats2half2_rn(v0, v1);
    }
    __syncthreads();

    // ---- accumulators seeded with bias ----
    const float bval = bias[0];
    float acc[2][4][4];
    #pragma unroll
    for (int m = 0; m < 2; ++m)
        #pragma unroll
        for (int j = 0; j < 4; ++j)
            #pragma unroll
            for (int e = 0; e < 4; ++e)
                acc[m][j][e] = bval;

    const uint32_t sA_b = smem_u32(sA);
    const uint32_t lanepart = sA_b + (uint32_t)((lane & 15) * (ASTRIDE * 2))
                            + (uint32_t)(64 * wx) + (uint32_t)((lane >> 4) << 4);
    const uint32_t sBf_b = smem_u32(sBf);
    const int rowbase = 32 * wy;

    #pragma unroll 1
    for (int dy = 0; dy < NDY; ++dy) {
        // --- batch ALL loads first: 4 B LDS.64 + 6 ldmatrix.x4, independent ---
        uint32_t b[NFRAG][2];
        #pragma unroll
        for (int d = 0; d < NFRAG; ++d) {
            uint32_t addr = sBf_b + (uint32_t)(((dy * NFRAG + d) * 32 + lane) * 8);
            asm volatile("ld.shared.v2.u32 {%0,%1}, [%2];"
                         : "=r"(b[d][0]), "=r"(b[d][1]) : "r"(addr));
        }
        const uint32_t r0 = lanepart + (uint32_t)((rowbase + dy)      * (ASTRIDE * 2));
        const uint32_t r1 = lanepart + (uint32_t)((rowbase + 16 + dy) * (ASTRIDE * 2));
        uint32_t a0[3][4], a1[3][4];
        ldmA(a0[0], r0);       ldmA(a0[1], r0 + 32);   ldmA(a0[2], r0 + 64);
        ldmA(a1[0], r1);       ldmA(a1[1], r1 + 32);   ldmA(a1[2], r1 + 64);

        // --- then 16 MMAs back-to-back ---
        #pragma unroll
        for (int qp = 0; qp < 2; ++qp)
            #pragma unroll
            for (int s = 0; s < 2; ++s) {
                float* c0 = acc[0][2 * qp + s];
                mma16816(c0, a0[qp],     b[1 - s][0], b[1 - s][1]);
                mma16816(c0, a0[qp + 1], b[3 - s][0], b[3 - s][1]);
                float* c1 = acc[1][2 * qp + s];
                mma16816(c1, a1[qp],     b[1 - s][0], b[1 - s][1]);
                mma16816(c1, a1[qp + 1], b[3 - s][0], b[3 - s][1]);
            }
    }

    // ---- epilogue: D fragments -> gmem (float2 stores) ----
    const int tg = lane & 3;
    const int gp = lane >> 2;
    #pragma unroll
    for (int mh = 0; mh < 2; ++mh)
        #pragma unroll
        for (int j = 0; j < 4; ++j) {
            const int col = X0 + 32 * wx + 8 * j + 2 * tg;
            const int r0  = Y0 + 32 * wy + 16 * mh + gp;
            if (col < OUT_N) {
                if (r0 < OUT_N) {
                    float2 v = make_float2(acc[mh][j][0], acc[mh][j][1]);
                    *reinterpret_cast<float2*>(&out[(size_t)r0 * OUT_N + col]) = v;
                }
                if (r0 + 8 < OUT_N) {
                    float2 v = make_float2(acc[mh][j][2], acc[mh][j][3]);
                    *reinterpret_cast<float2*>(&out[(size_t)(r0 + 8) * OUT_N + col]) = v;
                }
            }
        }
}

extern "C" void kernel_launch(void* const* d_in, const int* in_sizes, int n_in,
                              void* d_out, int out_size)
{
    const float* x    = (const float*)d_in[0];   // 4096*4096
    const float* w    = (const float*)d_in[1];   // 15*15
    const float* bias = (const float*)d_in[2];   // 1
    float* out        = (float*)d_out;           // 4084*4084

    prep_Bfrag<<<(NDY * NFRAG * 32 + 255) / 256, 256>>>(w);

    dim3 grid((OUT_N + CTA_X - 1) / CTA_X,       // 64
              (OUT_N + CTA_Y - 1) / CTA_Y);      // 32
    conv2d_mma_kernel<<<grid, 256>>>(x, bias, out);
}

// round 10
// speedup vs baseline: 1.4290x; 1.1332x over previous
#include <cuda_runtime.h>
#include <cuda_fp16.h>
#include <cstdint>

// Conv2D 4096x4096, 15x15, pad=1 -> 4084x4084, + bias.
// R10: warp tile 16y x 32x (one m-half), CTA 64y x 64x, 4096 CTAs.
// Low register state (acc 16) -> launch_bounds(256,5) -> ~62% occ.
// Per dy: batch 4 B LDS.64 + 3 ldmatrix.x4, then 8 MMAs.

#define KS      15
#define IN_N    4096
#define OUT_N   4084
#define CTA_Y   64             // 4 warps in y, 16 rows each
#define CTA_X   64             // 2 warps in x, 32 cols each
#define AROWS   78             // 64 + 14 halo
#define ACOLS   80             // 64 + 14 halo + 2 zero pad
#define ASTRIDE 88             // fp16/row; 176B rows, conflict-free ldmatrix
#define NDY     KS
#define NFRAG   4              // B fragments per dy (shifts -8, 0, +8, +16)

__device__ uint2 gBf[NDY * NFRAG * 32];   // B fragments in exact mma lane layout

__global__ void prep_Bfrag(const float* __restrict__ w)
{
    int idx = blockIdx.x * blockDim.x + threadIdx.x;
    if (idx >= NDY * NFRAG * 32) return;
    const int lane = idx & 31;
    const int d    = (idx >> 5) & 3;
    const int dy   = idx >> 7;
    const int tg   = lane & 3;
    const int gp   = lane >> 2;
    const int base = 8 * (d - 1) - gp;
    float v[4];
    #pragma unroll
    for (int q = 0; q < 4; ++q) {
        const int kl = 2 * tg + (q & 1) + 8 * (q >> 1);
        const int t  = base + kl;
        v[q] = (t >= 0 && t < KS) ? w[dy * KS + t] : 0.0f;
    }
    __half2 lo = __floats2half2_rn(v[0], v[1]);
    __half2 hi = __floats2half2_rn(v[2], v[3]);
    uint2 r;
    r.x = *reinterpret_cast<uint32_t*>(&lo);
    r.y = *reinterpret_cast<uint32_t*>(&hi);
    gBf[idx] = r;
}

__device__ __forceinline__ uint32_t smem_u32(const void* p)
{
    uint32_t a;
    asm("{ .reg .u64 t; cvta.to.shared.u64 t, %1; cvt.u32.u64 %0, t; }"
        : "=r"(a) : "l"(p));
    return a;
}
__device__ __forceinline__ void ldmA(uint32_t a[4], uint32_t addr)
{
    asm volatile("ldmatrix.sync.aligned.m8n8.x4.shared.b16 {%0,%1,%2,%3}, [%4];"
                 : "=r"(a[0]), "=r"(a[1]), "=r"(a[2]), "=r"(a[3]) : "r"(addr));
}
__device__ __forceinline__ void mma16816(float c[4], const uint32_t a[4],
                                         uint32_t b0, uint32_t b1)
{
    asm volatile(
        "mma.sync.aligned.m16n8k16.row.col.f32.f16.f16.f32 "
        "{%0,%1,%2,%3}, {%4,%5,%6,%7}, {%8,%9}, {%0,%1,%2,%3};"
        : "+f"(c[0]), "+f"(c[1]), "+f"(c[2]), "+f"(c[3])
        : "r"(a[0]), "r"(a[1]), "r"(a[2]), "r"(a[3]), "r"(b0), "r"(b1));
}

__global__ __launch_bounds__(256, 5)
void conv2d_mma16_kernel(const float* __restrict__ x,
                         const float* __restrict__ bias,
                         float* __restrict__ out)
{
    __shared__ __align__(32) __half sA[AROWS * ASTRIDE];   // 13728 B
    __shared__ uint2 sBf[NDY * NFRAG * 32];                // 15360 B

    const int tid  = threadIdx.x;
    const int lane = tid & 31;
    const int wid  = tid >> 5;
    const int wy   = wid >> 1;          // 0..3 (16 rows each)
    const int wx   = wid & 1;           // 0..1 (32 cols each)
    const int X0   = blockIdx.x * CTA_X;
    const int Y0   = blockIdx.y * CTA_Y;

    // ---- stage B fragments ----
    for (int i = tid; i < NDY * NFRAG * 32; i += 256)
        sBf[i] = gBf[i];

    // ---- stage A: 78 x 80 fp32 -> fp16 (smem col j <-> input col X0-1+j) ----
    for (int idx = tid; idx < AROWS * (ACOLS / 2); idx += 256) {
        const int r  = idx / (ACOLS / 2);
        const int p  = idx - r * (ACOLS / 2);
        const int gy = Y0 - 1 + r;
        const int gx = X0 - 1 + 2 * p;
        float v0 = 0.0f, v1 = 0.0f;
        if ((unsigned)gy < IN_N) {
            const float* rp = x + (size_t)gy * IN_N;
            if ((unsigned)gx       < IN_N) v0 = rp[gx];
            if ((unsigned)(gx + 1) < IN_N) v1 = rp[gx + 1];
        }
        *reinterpret_cast<__half2*>(&sA[r * ASTRIDE + 2 * p]) = __floats2half2_rn(v0, v1);
    }
    __syncthreads();

    // ---- accumulators seeded with bias (4 n-blocks x 4) ----
    const float bval = bias[0];
    float acc[4][4];
    #pragma unroll
    for (int j = 0; j < 4; ++j)
        #pragma unroll
        for (int e = 0; e < 4; ++e)
            acc[j][e] = bval;

    const uint32_t sA_b = smem_u32(sA);
    const uint32_t lanepart = sA_b + (uint32_t)((lane & 15) * (ASTRIDE * 2))
                            + (uint32_t)(64 * wx) + (uint32_t)((lane >> 4) << 4);
    const uint32_t sBf_b = smem_u32(sBf);
    const int rowbase = 16 * wy;

    #pragma unroll 1
    for (int dy = 0; dy < NDY; ++dy) {
        // --- batch loads: 4 B LDS.64 + 3 ldmatrix.x4, all independent ---
        uint32_t b[NFRAG][2];
        #pragma unroll
        for (int d = 0; d < NFRAG; ++d) {
            uint32_t addr = sBf_b + (uint32_t)(((dy * NFRAG + d) * 32 + lane) * 8);
            asm volatile("ld.shared.v2.u32 {%0,%1}, [%2];"
                         : "=r"(b[d][0]), "=r"(b[d][1]) : "r"(addr));
        }
        const uint32_t r0 = lanepart + (uint32_t)((rowbase + dy) * (ASTRIDE * 2));
        uint32_t a[3][4];
        ldmA(a[0], r0);
        ldmA(a[1], r0 + 32);
        ldmA(a[2], r0 + 64);

        // --- 8 MMAs back-to-back ---
        #pragma unroll
        for (int qp = 0; qp < 2; ++qp)
            #pragma unroll
            for (int s = 0; s < 2; ++s) {
                float* c = acc[2 * qp + s];
                mma16816(c, a[qp],     b[1 - s][0], b[1 - s][1]);
                mma16816(c, a[qp + 1], b[3 - s][0], b[3 - s][1]);
            }
    }

    // ---- epilogue: D fragments -> gmem (float2 stores) ----
    const int tg = lane & 3;
    const int gp = lane >> 2;
    #pragma unroll
    for (int j = 0; j < 4; ++j) {
        const int col = X0 + 32 * wx + 8 * j + 2 * tg;
        const int r0  = Y0 + 16 * wy + gp;
        if (col < OUT_N) {
            if (r0 < OUT_N) {
                float2 v = make_float2(acc[j][0], acc[j][1]);
                *reinterpret_cast<float2*>(&out[(size_t)r0 * OUT_N + col]) = v;
            }
            if (r0 + 8 < OUT_N) {
                float2 v = make_float2(acc[j][2], acc[j][3]);
                *reinterpret_cast<float2*>(&out[(size_t)(r0 + 8) * OUT_N + col]) = v;
            }
        }
    }
}

extern "C" void kernel_launch(void* const* d_in, const int* in_sizes, int n_in,
                              void* d_out, int out_size)
{
    const float* x    = (const float*)d_in[0];   // 4096*4096
    const float* w    = (const float*)d_in[1];   // 15*15
    const float* bias = (const float*)d_in[2];   // 1
    float* out        = (float*)d_out;           // 4084*4084

    prep_Bfrag<<<(NDY * NFRAG * 32 + 255) / 256, 256>>>(w);

    dim3 grid((OUT_N + CTA_X - 1) / CTA_X,       // 64
              (OUT_N + CTA_Y - 1) / CTA_Y);      // 64
    conv2d_mma16_kernel<<<grid, 256>>>(x, bias, out);
}

// round 11
// speedup vs baseline: 1.4705x; 1.0291x over previous
#include <cuda_runtime.h>
#include <cuda_fp16.h>
#include <cstdint>

// Conv2D 4096x4096, 15x15, pad=1 -> 4084x4084, + bias.
// R11: warp tile 16y x 64x, CTA 64y x 128x. A-window fragments shared across
// eight 8-col n-blocks -> 0.41 L1-wavefronts/output (R10: 0.59). Register
// control via window phasing (3 of 5 windows live), launch_bounds(256,4).

#define KS      15
#define IN_N    4096
#define OUT_N   4084
#define CTA_Y   64             // 4 warps in y, 16 rows each
#define CTA_X   128            // 2 warps in x, 64 cols each
#define AROWS   78             // 64 + 14 halo
#define ACOLS   144            // 128 + 14 halo + 2 zero pad
#define ASTRIDE 152            // fp16/row; 304B rows (%128==48) -> conflict-free
#define NDY     KS
#define NFRAG   4              // B fragments per dy (shifts -8, 0, +8, +16)

__device__ uint2 gBf[NDY * NFRAG * 32];   // B fragments in exact mma lane layout

__global__ void prep_Bfrag(const float* __restrict__ w)
{
    int idx = blockIdx.x * blockDim.x + threadIdx.x;
    if (idx >= NDY * NFRAG * 32) return;
    const int lane = idx & 31;
    const int d    = (idx >> 5) & 3;
    const int dy   = idx >> 7;
    const int tg   = lane & 3;
    const int gp   = lane >> 2;
    const int base = 8 * (d - 1) - gp;
    float v[4];
    #pragma unroll
    for (int q = 0; q < 4; ++q) {
        const int kl = 2 * tg + (q & 1) + 8 * (q >> 1);
        const int t  = base + kl;
        v[q] = (t >= 0 && t < KS) ? w[dy * KS + t] : 0.0f;
    }
    __half2 lo = __floats2half2_rn(v[0], v[1]);
    __half2 hi = __floats2half2_rn(v[2], v[3]);
    uint2 r;
    r.x = *reinterpret_cast<uint32_t*>(&lo);
    r.y = *reinterpret_cast<uint32_t*>(&hi);
    gBf[idx] = r;
}

__device__ __forceinline__ uint32_t smem_u32(const void* p)
{
    uint32_t a;
    asm("{ .reg .u64 t; cvta.to.shared.u64 t, %1; cvt.u32.u64 %0, t; }"
        : "=r"(a) : "l"(p));
    return a;
}
__device__ __forceinline__ void ldmA(uint32_t a[4], uint32_t addr)
{
    asm volatile("ldmatrix.sync.aligned.m8n8.x4.shared.b16 {%0,%1,%2,%3}, [%4];"
                 : "=r"(a[0]), "=r"(a[1]), "=r"(a[2]), "=r"(a[3]) : "r"(addr));
}
__device__ __forceinline__ void mma16816(float c[4], const uint32_t a[4],
                                         uint32_t b0, uint32_t b1)
{
    asm volatile(
        "mma.sync.aligned.m16n8k16.row.col.f32.f16.f16.f32 "
        "{%0,%1,%2,%3}, {%4,%5,%6,%7}, {%8,%9}, {%0,%1,%2,%3};"
        : "+f"(c[0]), "+f"(c[1]), "+f"(c[2]), "+f"(c[3])
        : "r"(a[0]), "r"(a[1]), "r"(a[2]), "r"(a[3]), "r"(b0), "r"(b1));
}

__global__ __launch_bounds__(256, 4)
void conv2d_mma1664_kernel(const float* __restrict__ x,
                           const float* __restrict__ bias,
                           float* __restrict__ out)
{
    __shared__ __align__(32) __half sA[AROWS * ASTRIDE];   // 23712 B
    __shared__ uint2 sBf[NDY * NFRAG * 32];                // 15360 B

    const int tid  = threadIdx.x;
    const int lane = tid & 31;
    const int wid  = tid >> 5;
    const int wy   = wid >> 1;          // 0..3 (16 rows each)
    const int wx   = wid & 1;           // 0..1 (64 cols each)
    const int X0   = blockIdx.x * CTA_X;
    const int Y0   = blockIdx.y * CTA_Y;

    // ---- stage B fragments ----
    for (int i = tid; i < NDY * NFRAG * 32; i += 256)
        sBf[i] = gBf[i];

    // ---- stage A: 78 x 144 fp32 -> fp16 (smem col j <-> input col X0-1+j);
    //      cols [142, 152) zero-filled ----
    for (int idx = tid; idx < AROWS * (ASTRIDE / 2); idx += 256) {
        const int r  = idx / (ASTRIDE / 2);
        const int p  = idx - r * (ASTRIDE / 2);
        const int c  = 2 * p;
        const int gy = Y0 - 1 + r;
        const int gx = X0 - 1 + c;
        float v0 = 0.0f, v1 = 0.0f;
        if (c < 142 && (unsigned)gy < IN_N) {
            const float* rp = x + (size_t)gy * IN_N;
            if ((unsigned)gx       < IN_N) v0 = rp[gx];
            if ((unsigned)(gx + 1) < IN_N && c + 1 < 142) v1 = rp[gx + 1];
        }
        *reinterpret_cast<__half2*>(&sA[r * ASTRIDE + c]) = __floats2half2_rn(v0, v1);
    }
    __syncthreads();

    // ---- accumulators seeded with bias (8 n-blocks x 4) ----
    const float bval = bias[0];
    float acc[8][4];
    #pragma unroll
    for (int j = 0; j < 8; ++j)
        #pragma unroll
        for (int e = 0; e < 4; ++e)
            acc[j][e] = bval;

    const uint32_t sA_b = smem_u32(sA);
    const uint32_t lanepart = sA_b + (uint32_t)((lane & 15) * (ASTRIDE * 2))
                            + (uint32_t)(128 * wx) + (uint32_t)((lane >> 4) << 4);
    const uint32_t sBf_b = smem_u32(sBf);
    const int rowbase = 16 * wy;

    #pragma unroll 1
    for (int dy = 0; dy < NDY; ++dy) {
        // --- B fragments + phase-A windows (w0,w1,w2), batched ---
        uint32_t b[NFRAG][2];
        #pragma unroll
        for (int d = 0; d < NFRAG; ++d) {
            uint32_t addr = sBf_b + (uint32_t)(((dy * NFRAG + d) * 32 + lane) * 8);
            asm volatile("ld.shared.v2.u32 {%0,%1}, [%2];"
                         : "=r"(b[d][0]), "=r"(b[d][1]) : "r"(addr));
        }
        const uint32_t r0 = lanepart + (uint32_t)((rowbase + dy) * (ASTRIDE * 2));
        uint32_t a0[4], a1[4], a2[4];
        ldmA(a0, r0);            // w0: cols  0-15
        ldmA(a1, r0 + 32);       // w1: cols 16-31
        ldmA(a2, r0 + 64);       // w2: cols 32-47

        // --- phase A: n-blocks 0..3 ---
        mma16816(acc[0], a0, b[1][0], b[1][1]);
        mma16816(acc[0], a1, b[3][0], b[3][1]);
        mma16816(acc[1], a0, b[0][0], b[0][1]);
        mma16816(acc[1], a1, b[2][0], b[2][1]);
        mma16816(acc[2], a1, b[1][0], b[1][1]);
        mma16816(acc[2], a2, b[3][0], b[3][1]);
        mma16816(acc[3], a1, b[0][0], b[0][1]);
        mma16816(acc[3], a2, b[2][0], b[2][1]);

        // --- reload w3,w4 over a0,a1 ---
        ldmA(a0, r0 + 96);       // w3: cols 48-63
        ldmA(a1, r0 + 128);      // w4: cols 64-79

        // --- phase B: n-blocks 4..7 ---
        mma16816(acc[4], a2, b[1][0], b[1][1]);
        mma16816(acc[4], a0, b[3][0], b[3][1]);
        mma16816(acc[5], a2, b[0][0], b[0][1]);
        mma16816(acc[5], a0, b[2][0], b[2][1]);
        mma16816(acc[6], a0, b[1][0], b[1][1]);
        mma16816(acc[6], a1, b[3][0], b[3][1]);
        mma16816(acc[7], a0, b[0][0], b[0][1]);
        mma16816(acc[7], a1, b[2][0], b[2][1]);
    }

    // ---- epilogue: D fragments -> gmem (float2 stores) ----
    const int tg = lane & 3;
    const int gp = lane >> 2;
    #pragma unroll
    for (int j = 0; j < 8; ++j) {
        const int col = X0 + 64 * wx + 8 * j + 2 * tg;
        const int r0  = Y0 + 16 * wy + gp;
        if (col < OUT_N) {
            if (r0 < OUT_N) {
                float2 v = make_float2(acc[j][0], acc[j][1]);
                *reinterpret_cast<float2*>(&out[(size_t)r0 * OUT_N + col]) = v;
            }
            if (r0 + 8 < OUT_N) {
                float2 v = make_float2(acc[j][2], acc[j][3]);
                *reinterpret_cast<float2*>(&out[(size_t)(r0 + 8) * OUT_N + col]) = v;
            }
        }
    }
}

extern "C" void kernel_launch(void* const* d_in, const int* in_sizes, int n_in,
                              void* d_out, int out_size)
{
    const float* x    = (const float*)d_in[0];   // 4096*4096
    const float* w    = (const float*)d_in[1];   // 15*15
    const float* bias = (const float*)d_in[2];   // 1
    float* out        = (float*)d_out;           // 4084*4084

    prep_Bfrag<<<(NDY * NFRAG * 32 + 255) / 256, 256>>>(w);

    dim3 grid((OUT_N + CTA_X - 1) / CTA_X,       // 32
              (OUT_N + CTA_Y - 1) / CTA_Y);      // 64
    conv2d_mma1664_kernel<<<grid, 256>>>(x, bias, out);
}

// round 12
// speedup vs baseline: 1.5689x; 1.0669x over previous
#include <cuda_runtime.h>
#include <cuda_fp16.h>
#include <cstdint>

// Conv2D 4096x4096, 15x15, pad=1 -> 4084x4084, + bias.
// R12: warp tile 16y x 48x, CTA 64y x 96x. Window-sharing (R11) at a 50-reg
// footprint -> launch_bounds(256,5) -> 5 CTAs/SM (40 warps). Rolling 3-buffer
// window schedule; ASTRIDE 240B (240/16 odd -> conflict-free ldmatrix).

#define KS      15
#define IN_N    4096
#define OUT_N   4084
#define CTA_Y   64             // 4 warps in y, 16 rows each
#define CTA_X   96             // 2 warps in x, 48 cols each
#define AROWS   78             // 64 + 14 halo
#define ACOLS   110            // 96 + 14 halo (cols [110,120) zero pad)
#define ASTRIDE 120            // fp16/row; 240B rows, 240/16=15 odd -> ldm conflict-free
#define NDY     KS
#define NFRAG   4              // B fragments per dy (shifts -8, 0, +8, +16)

__device__ uint2 gBf[NDY * NFRAG * 32];   // B fragments in exact mma lane layout

__global__ void prep_Bfrag(const float* __restrict__ w)
{
    int idx = blockIdx.x * blockDim.x + threadIdx.x;
    if (idx >= NDY * NFRAG * 32) return;
    const int lane = idx & 31;
    const int d    = (idx >> 5) & 3;
    const int dy   = idx >> 7;
    const int tg   = lane & 3;
    const int gp   = lane >> 2;
    const int base = 8 * (d - 1) - gp;
    float v[4];
    #pragma unroll
    for (int q = 0; q < 4; ++q) {
        const int kl = 2 * tg + (q & 1) + 8 * (q >> 1);
        const int t  = base + kl;
        v[q] = (t >= 0 && t < KS) ? w[dy * KS + t] : 0.0f;
    }
    __half2 lo = __floats2half2_rn(v[0], v[1]);
    __half2 hi = __floats2half2_rn(v[2], v[3]);
    uint2 r;
    r.x = *reinterpret_cast<uint32_t*>(&lo);
    r.y = *reinterpret_cast<uint32_t*>(&hi);
    gBf[idx] = r;
}

__device__ __forceinline__ uint32_t smem_u32(const void* p)
{
    uint32_t a;
    asm("{ .reg .u64 t; cvta.to.shared.u64 t, %1; cvt.u32.u64 %0, t; }"
        : "=r"(a) : "l"(p));
    return a;
}
__device__ __forceinline__ void ldmA(uint32_t a[4], uint32_t addr)
{
    asm volatile("ldmatrix.sync.aligned.m8n8.x4.shared.b16 {%0,%1,%2,%3}, [%4];"
                 : "=r"(a[0]), "=r"(a[1]), "=r"(a[2]), "=r"(a[3]) : "r"(addr));
}
__device__ __forceinline__ void mma16816(float c[4], const uint32_t a[4],
                                         uint32_t b0, uint32_t b1)
{
    asm volatile(
        "mma.sync.aligned.m16n8k16.row.col.f32.f16.f16.f32 "
        "{%0,%1,%2,%3}, {%4,%5,%6,%7}, {%8,%9}, {%0,%1,%2,%3};"
        : "+f"(c[0]), "+f"(c[1]), "+f"(c[2]), "+f"(c[3])
        : "r"(a[0]), "r"(a[1]), "r"(a[2]), "r"(a[3]), "r"(b0), "r"(b1));
}

__global__ __launch_bounds__(256, 5)
void conv2d_mma1648_kernel(const float* __restrict__ x,
                           const float* __restrict__ bias,
                           float* __restrict__ out)
{
    __shared__ __align__(32) __half sA[AROWS * ASTRIDE];   // 18720 B
    __shared__ uint2 sBf[NDY * NFRAG * 32];                // 15360 B

    const int tid  = threadIdx.x;
    const int lane = tid & 31;
    const int wid  = tid >> 5;
    const int wy   = wid >> 1;          // 0..3 (16 rows each)
    const int wx   = wid & 1;           // 0..1 (48 cols each)
    const int X0   = blockIdx.x * CTA_X;
    const int Y0   = blockIdx.y * CTA_Y;

    // ---- stage B fragments ----
    for (int i = tid; i < NDY * NFRAG * 32; i += 256)
        sBf[i] = gBf[i];

    // ---- stage A: 78 x 110 fp32 -> fp16 (smem col j <-> input col X0-1+j);
    //      cols [110, 120) zero-filled ----
    for (int idx = tid; idx < AROWS * (ASTRIDE / 2); idx += 256) {
        const int r  = idx / (ASTRIDE / 2);
        const int p  = idx - r * (ASTRIDE / 2);
        const int c  = 2 * p;
        const int gy = Y0 - 1 + r;
        const int gx = X0 - 1 + c;
        float v0 = 0.0f, v1 = 0.0f;
        if (c < ACOLS && (unsigned)gy < IN_N) {
            const float* rp = x + (size_t)gy * IN_N;
            if ((unsigned)gx       < IN_N) v0 = rp[gx];
            if ((unsigned)(gx + 1) < IN_N && c + 1 < ACOLS) v1 = rp[gx + 1];
        }
        *reinterpret_cast<__half2*>(&sA[r * ASTRIDE + c]) = __floats2half2_rn(v0, v1);
    }
    __syncthreads();

    // ---- accumulators seeded with bias (6 n-blocks x 4) ----
    const float bval = bias[0];
    float acc[6][4];
    #pragma unroll
    for (int j = 0; j < 6; ++j)
        #pragma unroll
        for (int e = 0; e < 4; ++e)
            acc[j][e] = bval;

    const uint32_t sA_b = smem_u32(sA);
    const uint32_t lanepart = sA_b + (uint32_t)((lane & 15) * (ASTRIDE * 2))
                            + (uint32_t)(96 * wx) + (uint32_t)((lane >> 4) << 4);
    const uint32_t sBf_b = smem_u32(sBf);
    const int rowbase = 16 * wy;

    #pragma unroll 1
    for (int dy = 0; dy < NDY; ++dy) {
        // --- batch: 4 B LDS.64 + 3 window ldmatrix.x4 (w0,w1,w2), MLP=7 ---
        uint32_t b[NFRAG][2];
        #pragma unroll
        for (int d = 0; d < NFRAG; ++d) {
            uint32_t addr = sBf_b + (uint32_t)(((dy * NFRAG + d) * 32 + lane) * 8);
            asm volatile("ld.shared.v2.u32 {%0,%1}, [%2];"
                         : "=r"(b[d][0]), "=r"(b[d][1]) : "r"(addr));
        }
        const uint32_t r0 = lanepart + (uint32_t)((rowbase + dy) * (ASTRIDE * 2));
        uint32_t wA[4], wB[4], wC[4];
        ldmA(wA, r0);            // w0: cols  0-15
        ldmA(wB, r0 + 32);       // w1: cols 16-31
        ldmA(wC, r0 + 64);       // w2: cols 32-47

        // --- nb0, nb1 (uses w0, w1) ---
        mma16816(acc[0], wA, b[1][0], b[1][1]);
        mma16816(acc[0], wB, b[3][0], b[3][1]);
        mma16816(acc[1], wA, b[0][0], b[0][1]);
        mma16816(acc[1], wB, b[2][0], b[2][1]);

        // --- w0 dead: reload as w3 (4 MMAs ahead of first use) ---
        ldmA(wA, r0 + 96);       // w3: cols 48-63

        // --- nb2, nb3 (uses w1, w2) ---
        mma16816(acc[2], wB, b[1][0], b[1][1]);
        mma16816(acc[2], wC, b[3][0], b[3][1]);
        mma16816(acc[3], wB, b[0][0], b[0][1]);
        mma16816(acc[3], wC, b[2][0], b[2][1]);

        // --- nb4, nb5 (uses w2, w3) ---
        mma16816(acc[4], wC, b[1][0], b[1][1]);
        mma16816(acc[4], wA, b[3][0], b[3][1]);
        mma16816(acc[5], wC, b[0][0], b[0][1]);
        mma16816(acc[5], wA, b[2][0], b[2][1]);
    }

    // ---- epilogue: D fragments -> gmem (float2 stores) ----
    const int tg = lane & 3;
    const int gp = lane >> 2;
    #pragma unroll
    for (int j = 0; j < 6; ++j) {
        const int col = X0 + 48 * wx + 8 * j + 2 * tg;
        const int r0  = Y0 + 16 * wy + gp;
        if (col < OUT_N) {
            if (r0 < OUT_N) {
                float2 v = make_float2(acc[j][0], acc[j][1]);
                *reinterpret_cast<float2*>(&out[(size_t)r0 * OUT_N + col]) = v;
            }
            if (r0 + 8 < OUT_N) {
                float2 v = make_float2(acc[j][2], acc[j][3]);
                *reinterpret_cast<float2*>(&out[(size_t)(r0 + 8) * OUT_N + col]) = v;
            }
        }
    }
}

extern "C" void kernel_launch(void* const* d_in, const int* in_sizes, int n_in,
                              void* d_out, int out_size)
{
    const float* x    = (const float*)d_in[0];   // 4096*4096
    const float* w    = (const float*)d_in[1];   // 15*15
    const float* bias = (const float*)d_in[2];   // 1
    float* out        = (float*)d_out;           // 4084*4084

    prep_Bfrag<<<(NDY * NFRAG * 32 + 255) / 256, 256>>>(w);

    dim3 grid((OUT_N + CTA_X - 1) / CTA_X,       // 43
              (OUT_N + CTA_Y - 1) / CTA_Y);      // 64
    conv2d_mma1648_kernel<<<grid, 256>>>(x, bias, out);
}

// round 14
// speedup vs baseline: 1.6232x; 1.0346x over previous
#include <cuda_runtime.h>
#include <cuda_fp16.h>
#include <cstdint>

// Conv2D 4096x4096, 15x15, pad=1 -> 4084x4084, + bias.
// R13: m16n8k8 MMAs — band of 15 taps covered by 3 k8 shifts (24 MAC/output
// vs 64 with k16): half the tensor work, B loads 8 wf -> 3 wf per dy.
// Warp tile 16y x 48x, CTA 64y x 96x, rolling 3-buffer windows, (256,5).

#define KS      15
#define IN_N    4096
#define OUT_N   4084
#define CTA_Y   64             // 4 warps in y, 16 rows each
#define CTA_X   96             // 2 warps in x, 48 cols each
#define AROWS   78             // 64 + 14 halo
#define ACOLS   110            // 96 + 14 halo (cols [110,120) zero pad)
#define ASTRIDE 120            // fp16/row; 240B rows, 240/16=15 odd -> ldm conflict-free
#define NDY     KS
#define NFRAG   4              // prep emits 4; k8 path uses d=1,2,3 (shifts 0,+8,+16)

__device__ uint2 gBf[NDY * NFRAG * 32];   // B fragments; .x reg is the k8 fragment

__global__ void prep_Bfrag(const float* __restrict__ w)
{
    int idx = blockIdx.x * blockDim.x + threadIdx.x;
    if (idx >= NDY * NFRAG * 32) return;
    const int lane = idx & 31;
    const int d    = (idx >> 5) & 3;
    const int dy   = idx >> 7;
    const int tg   = lane & 3;
    const int gp   = lane >> 2;
    const int base = 8 * (d - 1) - gp;
    float v[4];
    #pragma unroll
    for (int q = 0; q < 4; ++q) {
        const int kl = 2 * tg + (q & 1) + 8 * (q >> 1);
        const int t  = base + kl;
        v[q] = (t >= 0 && t < KS) ? w[dy * KS + t] : 0.0f;
    }
    __half2 lo = __floats2half2_rn(v[0], v[1]);
    __half2 hi = __floats2half2_rn(v[2], v[3]);
    uint2 r;
    r.x = *reinterpret_cast<uint32_t*>(&lo);   // k8 fragment: k = 2*tg+{0,1}, n = gp
    r.y = *reinterpret_cast<uint32_t*>(&hi);
    gBf[idx] = r;
}

__device__ __forceinline__ uint32_t smem_u32(const void* p)
{
    uint32_t a;
    asm("{ .reg .u64 t; cvta.to.shared.u64 t, %1; cvt.u32.u64 %0, t; }"
        : "=r"(a) : "l"(p));
    return a;
}
__device__ __forceinline__ void ldmA(uint32_t a[4], uint32_t addr)
{
    asm volatile("ldmatrix.sync.aligned.m8n8.x4.shared.b16 {%0,%1,%2,%3}, [%4];"
                 : "=r"(a[0]), "=r"(a[1]), "=r"(a[2]), "=r"(a[3]) : "r"(addr));
}
// m16n8k8: A = {a0,a1} (rows 0-15, one 8-col k window), B = 1 reg.
__device__ __forceinline__ void mma16808(float c[4], uint32_t a0, uint32_t a1,
                                         uint32_t b0)
{
    asm volatile(
        "mma.sync.aligned.m16n8k8.row.col.f32.f16.f16.f32 "
        "{%0,%1,%2,%3}, {%4,%5}, {%6}, {%0,%1,%2,%3};"
        : "+f"(c[0]), "+f"(c[1]), "+f"(c[2]), "+f"(c[3])
        : "r"(a0), "r"(a1), "r"(b0));
}

__global__ __launch_bounds__(256, 5)
void conv2d_mmak8_kernel(const float* __restrict__ x,
                         const float* __restrict__ bias,
                         float* __restrict__ out)
{
    __shared__ __align__(32) __half sA[AROWS * ASTRIDE];   // 18720 B
    __shared__ uint2 sBf[NDY * NFRAG * 32];                // 15360 B

    const int tid  = threadIdx.x;
    const int lane = tid & 31;
    const int wid  = tid >> 5;
    const int wy   = wid >> 1;          // 0..3 (16 rows each)
    const int wx   = wid & 1;           // 0..1 (48 cols each)
    const int X0   = blockIdx.x * CTA_X;
    const int Y0   = blockIdx.y * CTA_Y;

    // ---- stage B fragments ----
    for (int i = tid; i < NDY * NFRAG * 32; i += 256)
        sBf[i] = gBf[i];

    // ---- stage A: 78 x 110 fp32 -> fp16 (smem col j <-> input col X0-1+j);
    //      cols [110, 120) zero-filled ----
    for (int idx = tid; idx < AROWS * (ASTRIDE / 2); idx += 256) {
        const int r  = idx / (ASTRIDE / 2);
        const int p  = idx - r * (ASTRIDE / 2);
        const int c  = 2 * p;
        const int gy = Y0 - 1 + r;
        const int gx = X0 - 1 + c;
        float v0 = 0.0f, v1 = 0.0f;
        if (c < ACOLS && (unsigned)gy < IN_N) {
            const float* rp = x + (size_t)gy * IN_N;
            if ((unsigned)gx       < IN_N) v0 = rp[gx];
            if ((unsigned)(gx + 1) < IN_N && c + 1 < ACOLS) v1 = rp[gx + 1];
        }
        *reinterpret_cast<__half2*>(&sA[r * ASTRIDE + c]) = __floats2half2_rn(v0, v1);
    }
    __syncthreads();

    // ---- accumulators seeded with bias (6 n-blocks x 4) ----
    const float bval = bias[0];
    float acc[6][4];
    #pragma unroll
    for (int j = 0; j < 6; ++j)
        #pragma unroll
        for (int e = 0; e < 4; ++e)
            acc[j][e] = bval;

    const uint32_t sA_b = smem_u32(sA);
    const uint32_t lanepart = sA_b + (uint32_t)((lane & 15) * (ASTRIDE * 2))
                            + (uint32_t)(96 * wx) + (uint32_t)((lane >> 4) << 4);
    const uint32_t sBf_b = smem_u32(sBf);
    const int rowbase = 16 * wy;

    #pragma unroll 1
    for (int dy = 0; dy < NDY; ++dy) {
        // --- batch: 3 B LDS.32 (shifts 0,+8,+16 = prep d=1,2,3 .x reg)
        //     + 3 window ldmatrix.x4 (w0..w5), MLP=6 ---
        uint32_t b1, b2, b3;
        {
            const uint32_t ab = sBf_b + (uint32_t)((dy * NFRAG * 32 + lane) * 8);
            asm volatile("ld.shared.u32 %0, [%1];" : "=r"(b1) : "r"(ab + 1 * 32 * 8));
            asm volatile("ld.shared.u32 %0, [%1];" : "=r"(b2) : "r"(ab + 2 * 32 * 8));
            asm volatile("ld.shared.u32 %0, [%1];" : "=r"(b3) : "r"(ab + 3 * 32 * 8));
        }
        const uint32_t r0 = lanepart + (uint32_t)((rowbase + dy) * (ASTRIDE * 2));
        uint32_t wA[4], wB[4], wC[4];          // each holds 2 k8 windows
        ldmA(wA, r0);            // w0 (cols 0-7), w1 (8-15)
        ldmA(wB, r0 + 32);       // w2 (16-23), w3 (24-31)
        ldmA(wC, r0 + 64);       // w4 (32-39), w5 (40-47)

        // --- nb0: w0,w1,w2 ; nb1: w1,w2,w3 ---
        mma16808(acc[0], wA[0], wA[1], b1);
        mma16808(acc[0], wA[2], wA[3], b2);
        mma16808(acc[0], wB[0], wB[1], b3);
        mma16808(acc[1], wA[2], wA[3], b1);
        mma16808(acc[1], wB[0], wB[1], b2);
        mma16808(acc[1], wB[2], wB[3], b3);

        // --- wA dead: reload as w6,w7 (cols 48-63) ---
        ldmA(wA, r0 + 96);

        // --- nb2: w2,w3,w4 ; nb3: w3,w4,w5 ---
        mma16808(acc[2], wB[0], wB[1], b1);
        mma16808(acc[2], wB[2], wB[3], b2);
        mma16808(acc[2], wC[0], wC[1], b3);
        mma16808(acc[3], wB[2], wB[3], b1);
        mma16808(acc[3], wC[0], wC[1], b2);
        mma16808(acc[3], wC[2], wC[3], b3);

        // --- nb4: w4,w5,w6 ; nb5: w5,w6,w7 ---
        mma16808(acc[4], wC[0], wC[1], b1);
        mma16808(acc[4], wC[2], wC[3], b2);
        mma16808(acc[4], wA[0], wA[1], b3);
        mma16808(acc[5], wC[2], wC[3], b1);
        mma16808(acc[5], wA[0], wA[1], b2);
        mma16808(acc[5], wA[2], wA[3], b3);
    }

    // ---- epilogue: D fragments -> gmem (float2 stores) ----
    const int tg = lane & 3;
    const int gp = lane >> 2;
    #pragma unroll
    for (int j = 0; j < 6; ++j) {
        const int col = X0 + 48 * wx + 8 * j + 2 * tg;
        const int r0  = Y0 + 16 * wy + gp;
        if (col < OUT_N) {
            if (r0 < OUT_N) {
                float2 v = make_float2(acc[j][0], acc[j][1]);
                *reinterpret_cast<float2*>(&out[(size_t)r0 * OUT_N + col]) = v;
            }
            if (r0 + 8 < OUT_N) {
                float2 v = make_float2(acc[j][2], acc[j][3]);
                *reinterpret_cast<float2*>(&out[(size_t)(r0 + 8) * OUT_N + col]) = v;
            }
        }
    }
}

extern "C" void kernel_launch(void* const* d_in, const int* in_sizes, int n_in,
                              void* d_out, int out_size)
{
    const float* x    = (const float*)d_in[0];   // 4096*4096
    const float* w    = (const float*)d_in[1];   // 15*15
    const float* bias = (const float*)d_in[2];   // 1
    float* out        = (float*)d_out;           // 4084*4084

    prep_Bfrag<<<(NDY * NFRAG * 32 + 255) / 256, 256>>>(w);

    dim3 grid((OUT_N + CTA_X - 1) / CTA_X,       // 43
              (OUT_N + CTA_Y - 1) / CTA_Y);      // 64
    conv2d_mmak8_kernel<<<grid, 256>>>(x, bias, out);
}

// round 15
// speedup vs baseline: 1.6734x; 1.0309x over previous
#include <cuda_runtime.h>
#include <cuda_fp16.h>
#include <cstdint>

// Conv2D 4096x4096, 15x15, pad=1 -> 4084x4084, + bias.
// R15: k16 MMAs fed by shared k8 B-fragments. The 4 k16 band fragments per dy
// contain only 5 distinct 32-bit registers (shifts -8,0,+8,+16,+24):
// b[d] = (f[d], f[d+1]). 5 LDS.32 (5 wf) replaces 4 LDS.64 (8 wf), tensor work
// stays at 12 MMA/dy. Warp 16y x 48x, CTA 64y x 96x, rolling windows, (256,5).

#define KS      15
#define IN_N    4096
#define OUT_N   4084
#define CTA_Y   64             // 4 warps in y, 16 rows each
#define CTA_X   96             // 2 warps in x, 48 cols each
#define AROWS   78             // 64 + 14 halo
#define ACOLS   110            // 96 + 14 halo (cols [110,120) zero pad)
#define ASTRIDE 120            // fp16/row; 240B rows, 240/16=15 odd -> ldm conflict-free
#define NDY     KS
#define NF8     5              // distinct k8 fragments per dy (shifts -8,0,+8,+16,+24)

__device__ uint32_t gBf[NDY * NF8 * 32];   // k8 fragments in mma lane layout

// f[d], lane: t = 8*(d-1) + 2*(lane&3) + {0,1} - (lane>>2)
__global__ void prep_Bfrag(const float* __restrict__ w)
{
    int idx = blockIdx.x * blockDim.x + threadIdx.x;
    if (idx >= NDY * NF8 * 32) return;
    const int lane = idx & 31;
    const int d    = (idx / 32) % NF8;
    const int dy   = idx / (32 * NF8);
    const int tg   = lane & 3;
    const int gp   = lane >> 2;
    const int base = 8 * (d - 1) + 2 * tg - gp;
    float v0 = 0.0f, v1 = 0.0f;
    if (base >= 0     && base < KS)     v0 = w[dy * KS + base];
    if (base + 1 >= 0 && base + 1 < KS) v1 = w[dy * KS + base + 1];
    __half2 h = __floats2half2_rn(v0, v1);
    gBf[idx] = *reinterpret_cast<uint32_t*>(&h);
}

__device__ __forceinline__ uint32_t smem_u32(const void* p)
{
    uint32_t a;
    asm("{ .reg .u64 t; cvta.to.shared.u64 t, %1; cvt.u32.u64 %0, t; }"
        : "=r"(a) : "l"(p));
    return a;
}
__device__ __forceinline__ void ldmA(uint32_t a[4], uint32_t addr)
{
    asm volatile("ldmatrix.sync.aligned.m8n8.x4.shared.b16 {%0,%1,%2,%3}, [%4];"
                 : "=r"(a[0]), "=r"(a[1]), "=r"(a[2]), "=r"(a[3]) : "r"(addr));
}
__device__ __forceinline__ void mma16816(float c[4], const uint32_t a[4],
                                         uint32_t b0, uint32_t b1)
{
    asm volatile(
        "mma.sync.aligned.m16n8k16.row.col.f32.f16.f16.f32 "
        "{%0,%1,%2,%3}, {%4,%5,%6,%7}, {%8,%9}, {%0,%1,%2,%3};"
        : "+f"(c[0]), "+f"(c[1]), "+f"(c[2]), "+f"(c[3])
        : "r"(a[0]), "r"(a[1]), "r"(a[2]), "r"(a[3]), "r"(b0), "r"(b1));
}

__global__ __launch_bounds__(256, 5)
void conv2d_mma_k16s_kernel(const float* __restrict__ x,
                            const float* __restrict__ bias,
                            float* __restrict__ out)
{
    __shared__ __align__(32) __half sA[AROWS * ASTRIDE];   // 18720 B
    __shared__ uint32_t sBf[NDY * NF8 * 32];               // 9600 B

    const int tid  = threadIdx.x;
    const int lane = tid & 31;
    const int wid  = tid >> 5;
    const int wy   = wid >> 1;          // 0..3 (16 rows each)
    const int wx   = wid & 1;           // 0..1 (48 cols each)
    const int X0   = blockIdx.x * CTA_X;
    const int Y0   = blockIdx.y * CTA_Y;

    // ---- stage B fragments ----
    for (int i = tid; i < NDY * NF8 * 32; i += 256)
        sBf[i] = gBf[i];

    // ---- stage A: 78 x 110 fp32 -> fp16 (smem col j <-> input col X0-1+j);
    //      cols [110, 120) zero-filled ----
    for (int idx = tid; idx < AROWS * (ASTRIDE / 2); idx += 256) {
        const int r  = idx / (ASTRIDE / 2);
        const int p  = idx - r * (ASTRIDE / 2);
        const int c  = 2 * p;
        const int gy = Y0 - 1 + r;
        const int gx = X0 - 1 + c;
        float v0 = 0.0f, v1 = 0.0f;
        if (c < ACOLS && (unsigned)gy < IN_N) {
            const float* rp = x + (size_t)gy * IN_N;
            if ((unsigned)gx       < IN_N) v0 = rp[gx];
            if ((unsigned)(gx + 1) < IN_N && c + 1 < ACOLS) v1 = rp[gx + 1];
        }
        *reinterpret_cast<__half2*>(&sA[r * ASTRIDE + c]) = __floats2half2_rn(v0, v1);
    }
    __syncthreads();

    // ---- accumulators seeded with bias (6 n-blocks x 4) ----
    const float bval = bias[0];
    float acc[6][4];
    #pragma unroll
    for (int j = 0; j < 6; ++j)
        #pragma unroll
        for (int e = 0; e < 4; ++e)
            acc[j][e] = bval;

    const uint32_t sA_b = smem_u32(sA);
    const uint32_t lanepart = sA_b + (uint32_t)((lane & 15) * (ASTRIDE * 2))
                            + (uint32_t)(96 * wx) + (uint32_t)((lane >> 4) << 4);
    const uint32_t sBf_b = smem_u32(sBf);
    const int rowbase = 16 * wy;

    #pragma unroll 1
    for (int dy = 0; dy < NDY; ++dy) {
        // --- batch: 5 B LDS.32 (k8 fragments f0..f4) + 3 ldmatrix.x4, MLP=8 ---
        uint32_t f0, f1, f2, f3, f4;
        {
            const uint32_t ab = sBf_b + (uint32_t)((dy * NF8 * 32 + lane) * 4);
            asm volatile("ld.shared.u32 %0, [%1];" : "=r"(f0) : "r"(ab));
            asm volatile("ld.shared.u32 %0, [%1];" : "=r"(f1) : "r"(ab + 1 * 128));
            asm volatile("ld.shared.u32 %0, [%1];" : "=r"(f2) : "r"(ab + 2 * 128));
            asm volatile("ld.shared.u32 %0, [%1];" : "=r"(f3) : "r"(ab + 3 * 128));
            asm volatile("ld.shared.u32 %0, [%1];" : "=r"(f4) : "r"(ab + 4 * 128));
        }
        const uint32_t r0 = lanepart + (uint32_t)((rowbase + dy) * (ASTRIDE * 2));
        uint32_t wA[4], wB[4], wC[4];
        ldmA(wA, r0);            // cols  0-15
        ldmA(wB, r0 + 32);       // cols 16-31
        ldmA(wC, r0 + 64);       // cols 32-47

        // k16 band fragments: b[d] = (f[d], f[d+1]), shifts -8,0,+8,+16
        // --- nb0, nb1 (wA, wB) ---
        mma16816(acc[0], wA, f1, f2);      // b[1]
        mma16816(acc[0], wB, f3, f4);      // b[3]
        mma16816(acc[1], wA, f0, f1);      // b[0]
        mma16816(acc[1], wB, f2, f3);      // b[2]

        // --- wA dead: reload cols 48-63 ---
        ldmA(wA, r0 + 96);

        // --- nb2, nb3 (wB, wC) ---
        mma16816(acc[2], wB, f1, f2);
        mma16816(acc[2], wC, f3, f4);
        mma16816(acc[3], wB, f0, f1);
        mma16816(acc[3], wC, f2, f3);

        // --- nb4, nb5 (wC, wA) ---
        mma16816(acc[4], wC, f1, f2);
        mma16816(acc[4], wA, f3, f4);
        mma16816(acc[5], wC, f0, f1);
        mma16816(acc[5], wA, f2, f3);
    }

    // ---- epilogue: D fragments -> gmem (float2 stores) ----
    const int tg = lane & 3;
    const int gp = lane >> 2;
    #pragma unroll
    for (int j = 0; j < 6; ++j) {
        const int col = X0 + 48 * wx + 8 * j + 2 * tg;
        const int r0  = Y0 + 16 * wy + gp;
        if (col < OUT_N) {
            if (r0 < OUT_N) {
                float2 v = make_float2(acc[j][0], acc[j][1]);
                *reinterpret_cast<float2*>(&out[(size_t)r0 * OUT_N + col]) = v;
            }
            if (r0 + 8 < OUT_N) {
                float2 v = make_float2(acc[j][2], acc[j][3]);
                *reinterpret_cast<float2*>(&out[(size_t)(r0 + 8) * OUT_N + col]) = v;
            }
        }
    }
}

extern "C" void kernel_launch(void* const* d_in, const int* in_sizes, int n_in,
                              void* d_out, int out_size)
{
    const float* x    = (const float*)d_in[0];   // 4096*4096
    const float* w    = (const float*)d_in[1];   // 15*15
    const float* bias = (const float*)d_in[2];   // 1
    float* out        = (float*)d_out;           // 4084*4084

    prep_Bfrag<<<(NDY * NF8 * 32 + 255) / 256, 256>>>(w);

    dim3 grid((OUT_N + CTA_X - 1) / CTA_X,       // 43
              (OUT_N + CTA_Y - 1) / CTA_Y);      // 64
    conv2d_mma_k16s_kernel<<<grid, 256>>>(x, bias, out);
}